// round 17
// baseline (speedup 1.0000x reference)
#include <cuda_runtime.h>
#include <cuda_fp16.h>

#define NV 5
#define NC 32
#define ND 48
#define NH 128
#define NW 160
#define HW (NH*NW)        /* 20480 */
#define DHW (ND*HW)       /* 983040 */
#define RATIO 8
#define NTASK (5*NH*2)    /* (w-strips) * h * depth-halves = 1280 */

// Scratch (device globals — no allocation allowed)
__device__ float g_feat[NV*HW*NC];          // (v, h, w, c) channels-last fp32, 13.1 MB
__device__ float g_B[(size_t)9*DHW];        // 9 hw-tap fields (kd folded), 35.4 MB
__device__ float g_rot[NV][9];
__device__ float g_trans[NV][3];
__device__ int   g_ctr;                     // work-stealing task counter

// ---------------------------------------------------------------------------
// 1) Projection setup (double precision) + task-counter reset
// ---------------------------------------------------------------------------
__global__ void proj_kernel(const float* __restrict__ proj) {
    if (threadIdx.x != 0) return;
    g_ctr = 0;
    double comb[NV][16];
    for (int v = 0; v < NV; v++) {
        const float* E = proj + v*32;
        const float* P = proj + v*32 + 16;
        for (int r = 0; r < 3; r++)
            for (int c = 0; c < 4; c++) {
                double s = 0.0;
                for (int k = 0; k < 3; k++) s += (double)P[r*4+k] * (double)E[k*4+c];
                comb[v][r*4+c] = s;
            }
        for (int c = 0; c < 4; c++) comb[v][12+c] = (double)E[12+c];
    }
    double a[4][8];
    for (int i = 0; i < 4; i++)
        for (int j = 0; j < 4; j++) { a[i][j] = comb[0][i*4+j]; a[i][4+j] = (i==j) ? 1.0 : 0.0; }
    for (int col = 0; col < 4; col++) {
        int p = col;
        for (int r = col+1; r < 4; r++) if (fabs(a[r][col]) > fabs(a[p][col])) p = r;
        if (p != col) for (int j = 0; j < 8; j++) { double t = a[col][j]; a[col][j] = a[p][j]; a[p][j] = t; }
        double inv = 1.0 / a[col][col];
        for (int j = 0; j < 8; j++) a[col][j] *= inv;
        for (int r = 0; r < 4; r++) if (r != col) {
            double f = a[r][col];
            for (int j = 0; j < 8; j++) a[r][j] -= f * a[col][j];
        }
    }
    for (int v = 1; v < NV; v++) {
        double Pm[16];
        for (int i = 0; i < 4; i++)
            for (int j = 0; j < 4; j++) {
                double s = 0.0;
                for (int k = 0; k < 4; k++) s += comb[v][i*4+k] * a[k][4+j];
                Pm[i*4+j] = s;
            }
        for (int i = 0; i < 3; i++) {
            for (int j = 0; j < 3; j++) g_rot[v][i*3+j] = (float)Pm[i*4+j];
            g_trans[v][i] = (float)Pm[i*4+3];
        }
    }
}

// ---------------------------------------------------------------------------
// 2) Features (V,C,H,W) -> (V,H,W,C) channels-last (fp32)
// ---------------------------------------------------------------------------
__global__ __launch_bounds__(256) void transpose_kernel(const float* __restrict__ f) {
    __shared__ float t[32][33];
    int w0 = blockIdx.x * 32, h = blockIdx.y, v = blockIdx.z;
    int tid = threadIdx.x;
    #pragma unroll
    for (int e = tid; e < 1024; e += 256) {
        int c = e >> 5, w = e & 31;
        t[c][w] = f[((size_t)(v*NC + c)*NH + h)*NW + w0 + w];
    }
    __syncthreads();
    #pragma unroll
    for (int e = tid; e < 1024; e += 256) {
        int w = e >> 5, c = e & 31;
        g_feat[((size_t)((v*NH + h)*NW) + w0 + w)*NC + c] = t[c][w];
    }
}

// ---------------------------------------------------------------------------
// 3) FUSED warp+variance+contraction+kd-fold — PERSISTENT, WARP-SPECIALIZED,
//    half2 variance exchange, depth-paired Phase B (R16 body, unchanged).
// ---------------------------------------------------------------------------
__global__ __launch_bounds__(288, 4) void warpvar_kernel(const float* __restrict__ dvals,
                                                         const float* __restrict__ Wreg) {
    int tid  = threadIdx.x;
    int lane = tid & 31, wid = tid >> 5;     // wid 0..8
    int sub = lane >> 3, q = lane & 7;
    int p  = wid * 4 + sub;                  // point 0..31 (gather warps)
    bool doA = (wid < 8);

    __shared__ float swt[9][3][NC];          // [tap9][kd][c]
    __shared__ float sdep[ND];
    __shared__ float srot[NV-1][9];
    __shared__ float strn[NV-1][3];
    __shared__ __half2 svh[2][16][34];       // variance planes (d, d+1)
    __shared__ float4 spw[4][NV-1][32];      // staged bilinear weights (slot = d&3)
    __shared__ int4   spo[4][NV-1][32];      // staged gather offsets (16B units)
    __shared__ int s_task;

    for (int e = tid; e < 9*3*NC; e += 288) {
        int c = e & 31; int kd = (e >> 5) % 3; int t9 = e / 96;
        swt[t9][kd][c] = Wreg[c*27 + kd*9 + t9];
    }
    if (tid < ND) sdep[tid] = dvals[tid];
    if (tid < (NV-1)*9) srot[tid/9][tid%9] = g_rot[tid/9 + 1][tid%9];
    if (tid < (NV-1)*3) strn[tid/3][tid%3] = g_trans[tid/3 + 1][tid%3];

    const float4* wk0 = (const float4*)&swt[wid][0][0];
    const float4* wk1 = (const float4*)&swt[wid][1][0];
    const float4* wk2 = (const float4*)&swt[wid][2][0];
    const float inv5 = 1.f / (float)NV;

    while (true) {
        if (tid == 0) s_task = atomicAdd(&g_ctr, 1);
        __syncthreads();                     // also orders smem init on first pass
        int t = s_task;
        if (t >= NTASK) break;

        int dhalf = t & 1;
        int strip = t >> 1;
        int w0 = (strip % 5) * 32;
        int h  = strip / 5;

        int odlo = dhalf * (ND/2), odhi = odlo + ND/2 - 1;
        int dlo = (odlo - 1 < 0) ? 0 : odlo - 1;
        int dhi = (odhi + 1 > ND-1) ? ND-1 : odhi + 1;

        auto produce = [&](float dep, int pb) {
            float fw = (float)(w0 + lane), fh = (float)h;
            #pragma unroll
            for (int v = 0; v < NV-1; v++) {
                const float* R = srot[v];
                const float* T = strn[v];
                float px = (R[0]*fw + R[1]*fh + R[2]) * dep + T[0];
                float py = (R[3]*fw + R[4]*fh + R[5]) * dep + T[1];
                float pz = (R[6]*fw + R[7]*fh + R[8]) * dep + T[2];
                float rzi = __fdividef(1.f, pz);
                float gx = px * rzi, gy = py * rzi;
                float x0f = floorf(gx), y0f = floorf(gy);
                float wx = gx - x0f, wy = gy - y0f;
                float x1f = x0f + 1.f, y1f = y0f + 1.f;
                float vx0 = (x0f >= 0.f && x0f <= (float)(NW-1)) ? 1.f : 0.f;
                float vx1 = (x1f >= 0.f && x1f <= (float)(NW-1)) ? 1.f : 0.f;
                float vy0 = (y0f >= 0.f && y0f <= (float)(NH-1)) ? 1.f : 0.f;
                float vy1 = (y1f >= 0.f && y1f <= (float)(NH-1)) ? 1.f : 0.f;
                float w00 = (1.f-wx)*(1.f-wy) * vx0 * vy0;
                float w10 = wx*(1.f-wy)       * vx1 * vy0;
                float w01 = (1.f-wx)*wy       * vx0 * vy1;
                float w11 = wx*wy             * vx1 * vy1;
                int x0 = (int)fminf(fmaxf(x0f, 0.f), (float)(NW-1));
                int x1 = (int)fminf(fmaxf(x1f, 0.f), (float)(NW-1));
                int y0 = (int)fminf(fmaxf(y0f, 0.f), (float)(NH-1));
                int y1 = (int)fminf(fmaxf(y1f, 0.f), (float)(NH-1));
                int ox0 = x0*8, ox1 = x1*8;                 // float4 units
                int oy0 = y0*(NW*8), oy1 = y1*(NW*8);
                spw[pb][v][lane] = make_float4(w00, w10, w01, w11);
                spo[pb][v][lane] = make_int4(oy0+ox0, oy0+ox1, oy1+ox0, oy1+ox1);
            }
        };

        float4 ref, ref2;
        if (doA) {
            int w = w0 + p;
            ref = ((const float4*)(g_feat + (size_t)(h*NW + w)*NC))[q];
            ref2 = make_float4(ref.x*ref.x, ref.y*ref.y, ref.z*ref.z, ref.w*ref.w);
        }

        auto gather_var = [&](int pb, int pl) {
            float4 vs = ref, vq = ref2;
            #pragma unroll
            for (int v = 0; v < NV-1; v++) {
                float4 wts = spw[pb][v][p];        // broadcast LDS.128
                int4   of  = spo[pb][v][p];
                const float4* base = (const float4*)g_feat + (size_t)(v+1)*HW*8;
                float4 wv = make_float4(0.f, 0.f, 0.f, 0.f);
                if (wts.x + wts.y > 1e-4f) {
                    float4 a = base[of.x + q];
                    float4 b = base[of.y + q];
                    wv.x = wts.x*a.x + wts.y*b.x;
                    wv.y = wts.x*a.y + wts.y*b.y;
                    wv.z = wts.x*a.z + wts.y*b.z;
                    wv.w = wts.x*a.w + wts.y*b.w;
                }
                if (wts.z + wts.w > 1e-4f) {
                    float4 c4 = base[of.z + q];
                    float4 e4 = base[of.w + q];
                    wv.x += wts.z*c4.x + wts.w*e4.x;
                    wv.y += wts.z*c4.y + wts.w*e4.y;
                    wv.z += wts.z*c4.z + wts.w*e4.z;
                    wv.w += wts.z*c4.w + wts.w*e4.w;
                }
                vs.x += wv.x; vs.y += wv.y; vs.z += wv.z; vs.w += wv.w;
                vq.x += wv.x*wv.x; vq.y += wv.y*wv.y; vq.z += wv.z*wv.z; vq.w += wv.w*wv.w;
            }
            float mx = vs.x*inv5, my = vs.y*inv5, mz = vs.z*inv5, mw = vs.w*inv5;
            float2 v01 = make_float2(vq.x*inv5 - mx*mx, vq.y*inv5 - my*my);
            float2 v23 = make_float2(vq.z*inv5 - mz*mz, vq.w*inv5 - mw*mw);
            svh[pl][2*q+0][p] = __float22half2_rn(v01);
            svh[pl][2*q+1][p] = __float22half2_rn(v23);
        };

        float aP = 0.f, aC = 0.f, aN = 0.f;
        const size_t hwbase = (size_t)h*NW + w0 + lane;

        auto ring = [&](float d0, float d1, float d2, int d) {
            aN += d0; aC += d1; aP += d2;        // od = d+1, d, d-1
            int od = d - 1;
            if (od >= odlo && od <= odhi)
                g_B[(size_t)wid*DHW + (size_t)od*HW + hwbase] = aP;
            aP = aC; aC = aN; aN = 0.f;
        };

        if (!doA) { produce(sdep[dlo], dlo & 3); produce(sdep[dlo+1], (dlo+1) & 3); }
        __syncthreads();

        int d = dlo;
        for (; d + 1 <= dhi; d += 2) {
            if (doA) {
                gather_var(d & 3, 0);
                gather_var((d+1) & 3, 1);
            } else {
                if (d + 2 <= dhi) produce(sdep[d+2], (d+2) & 3);
                if (d + 3 <= dhi) produce(sdep[d+3], (d+3) & 3);
            }
            __syncthreads();

            float a0 = 0.f, a1 = 0.f, a2 = 0.f;
            float b0 = 0.f, b1 = 0.f, b2 = 0.f;
            #pragma unroll
            for (int c4 = 0; c4 < 8; c4++) {
                float2 fa0 = __half22float2(svh[0][2*c4+0][lane]);
                float2 fb0 = __half22float2(svh[0][2*c4+1][lane]);
                float2 fa1 = __half22float2(svh[1][2*c4+0][lane]);
                float2 fb1 = __half22float2(svh[1][2*c4+1][lane]);
                float4 u0 = wk0[c4], u1 = wk1[c4], u2 = wk2[c4];
                a0 += fa0.x*u0.x + fa0.y*u0.y + fb0.x*u0.z + fb0.y*u0.w;
                a1 += fa0.x*u1.x + fa0.y*u1.y + fb0.x*u1.z + fb0.y*u1.w;
                a2 += fa0.x*u2.x + fa0.y*u2.y + fb0.x*u2.z + fb0.y*u2.w;
                b0 += fa1.x*u0.x + fa1.y*u0.y + fb1.x*u0.z + fb1.y*u0.w;
                b1 += fa1.x*u1.x + fa1.y*u1.y + fb1.x*u1.z + fb1.y*u1.w;
                b2 += fa1.x*u2.x + fa1.y*u2.y + fb1.x*u2.z + fb1.y*u2.w;
            }
            ring(a0, a1, a2, d);
            ring(b0, b1, b2, d + 1);
            __syncthreads();
        }
        if (d <= dhi) {
            if (doA) gather_var(d & 3, 0);
            __syncthreads();
            float a0 = 0.f, a1 = 0.f, a2 = 0.f;
            #pragma unroll
            for (int c4 = 0; c4 < 8; c4++) {
                float2 fa0 = __half22float2(svh[0][2*c4+0][lane]);
                float2 fb0 = __half22float2(svh[0][2*c4+1][lane]);
                float4 u0 = wk0[c4], u1 = wk1[c4], u2 = wk2[c4];
                a0 += fa0.x*u0.x + fa0.y*u0.y + fb0.x*u0.z + fb0.y*u0.w;
                a1 += fa0.x*u1.x + fa0.y*u1.y + fb0.x*u1.z + fb0.y*u1.w;
                a2 += fa0.x*u2.x + fa0.y*u2.y + fb0.x*u2.z + fb0.y*u2.w;
            }
            ring(a0, a1, a2, d);
        }
        if (odhi == ND-1)
            g_B[(size_t)wid*DHW + (size_t)(ND-1)*HW + hwbase] = aP;
    }
}

// ---------------------------------------------------------------------------
// 4) FUSED conv-tail + softmax + depth + conf: one thread per (h,w) does the
//    9-tap shifted sums for all 48 depths into registers (same summation
//    order as the old gathersum), then the softmax chain inline — no g_pre
//    round-trip.
// ---------------------------------------------------------------------------
__global__ __launch_bounds__(256) void convsoft_kernel(const float* __restrict__ dvals,
                                                       float* __restrict__ odepth,
                                                       float* __restrict__ oconf) {
    int w = blockIdx.x*32 + threadIdx.x;
    int h = blockIdx.y*8  + threadIdx.y;

    float p[ND];
    float mx = -1e30f;
    #pragma unroll
    for (int d = 0; d < ND; d++) {
        float s = 0.f;
        #pragma unroll
        for (int kh = 0; kh < 3; kh++) {
            int hh = h + kh - 1;
            if (hh < 0 || hh >= NH) continue;
            size_t rowb = (size_t)d*HW + (size_t)hh*NW;
            #pragma unroll
            for (int kw = 0; kw < 3; kw++) {
                int ww = w + kw - 1;
                if (ww < 0 || ww >= NW) continue;
                int tap = kh*3 + kw;
                s += g_B[(size_t)tap*DHW + rowb + ww];
            }
        }
        p[d] = s;
        mx = fmaxf(mx, s);
    }

    float s = 0.f;
    #pragma unroll
    for (int dd = 0; dd < ND; dd++) { p[dd] = expf(p[dd] - mx); s += p[dd]; }
    float inv = 1.f / s;
    float depth = 0.f, fi = 0.f;
    #pragma unroll
    for (int dd = 0; dd < ND; dd++) {
        float pr = p[dd] * inv;
        depth += pr * dvals[dd];
        fi    += pr * (float)dd;
    }
    int di = (int)fi;
    di = max(0, min(ND-1, di));
    float conf = 0.f;
    #pragma unroll
    for (int dd = 0; dd < ND; dd++)
        if (dd >= di-1 && dd <= di+2) conf += p[dd] * inv;
    int idx = h*NW + w;
    odepth[idx] = depth;
    oconf[idx]  = conf;
}

// ---------------------------------------------------------------------------
// 5) Convex upsample x8 — one thread per (i, h, even-w pair): mask reads as
//    float2 (half the load instructions), identical per-pixel arithmetic.
// ---------------------------------------------------------------------------
__global__ __launch_bounds__(256) void upsample_kernel(const float* __restrict__ mask,
                                                       const float* __restrict__ depth,
                                                       float* __restrict__ out) {
    int idx = blockIdx.x*blockDim.x + threadIdx.x;   // over RATIO*HW/2
    const int HW2 = HW/2, NW2 = NW/2;
    if (idx >= RATIO*HW2) return;
    int i    = idx / HW2;
    int rem2 = idx - i*HW2;
    int h    = rem2 / NW2;
    int w    = (rem2 - h*NW2) * 2;                   // even w
    int rem  = h*NW + w;

    // 3x4 depth neighborhood covering pixels w and w+1
    float nb[3][4];
    #pragma unroll
    for (int dy = 0; dy < 3; dy++)
        #pragma unroll
        for (int dx = 0; dx < 4; dx++) {
            int hh = h + dy - 1, ww = w + dx - 1;
            nb[dy][dx] = (hh >= 0 && hh < NH && ww >= 0 && ww < NW) ? depth[hh*NW + ww] : 0.f;
        }

    float val0[8], val1[8];
    #pragma unroll
    for (int j = 0; j < 8; j++) {
        float2 m[9];
        float mx0 = -1e30f, mx1 = -1e30f;
        #pragma unroll
        for (int k = 0; k < 9; k++) {
            m[k] = *(const float2*)(mask + (size_t)((k*8 + i)*8 + j)*HW + rem);
            mx0 = fmaxf(mx0, m[k].x);
            mx1 = fmaxf(mx1, m[k].y);
        }
        float s0 = 0.f, acc0 = 0.f, s1 = 0.f, acc1 = 0.f;
        #pragma unroll
        for (int k = 0; k < 9; k++) {
            int dy = k/3, dx = k%3;
            float e0 = __expf(m[k].x - mx0);
            s0 += e0; acc0 += e0 * nb[dy][dx];
            float e1 = __expf(m[k].y - mx1);
            s1 += e1; acc1 += e1 * nb[dy][dx+1];
        }
        val0[j] = acc0 / s0;
        val1[j] = acc1 / s1;
    }
    float* o = out + (size_t)(h*8 + i)*(NW*8) + w*8;
    float4* o4 = (float4*)o;
    o4[0] = make_float4(val0[0], val0[1], val0[2], val0[3]);
    o4[1] = make_float4(val0[4], val0[5], val0[6], val0[7]);
    o4[2] = make_float4(val1[0], val1[1], val1[2], val1[3]);
    o4[3] = make_float4(val1[4], val1[5], val1[6], val1[7]);
}

// ---------------------------------------------------------------------------
extern "C" void kernel_launch(void* const* d_in, const int* in_sizes, int n_in,
                              void* d_out, int out_size) {
    const float* features = (const float*)d_in[0];  // (V,B,C,H,W)
    const float* proj     = (const float*)d_in[1];  // (B,V,2,4,4)
    const float* dvals    = (const float*)d_in[2];  // (B,D)
    const float* mask     = (const float*)d_in[3];  // (B,576,H,W)
    const float* Wreg     = (const float*)d_in[4];  // (1,C,3,3,3)

    float* out       = (float*)d_out;
    float* out_depth = out + (size_t)NH*RATIO*NW*RATIO;   // after depth_up
    float* out_conf  = out_depth + HW;

    proj_kernel<<<1, 32>>>(proj);                                    // launch 1 (+ctr reset)
    transpose_kernel<<<dim3(NW/32, NH, NV), 256>>>(features);        // launch 2
    warpvar_kernel<<<592, 288>>>(dvals, Wreg);                       // launch 3 (148*4)
    convsoft_kernel<<<dim3(NW/32, NH/8), dim3(32, 8)>>>(dvals, out_depth, out_conf); // launch 4
    upsample_kernel<<<(RATIO*HW/2)/256, 256>>>(mask, out_depth, out);// launch 5
}